// round 17
// baseline (speedup 1.0000x reference)
#include <cuda_runtime.h>
#include <cuda_bf16.h>
#include <math.h>

// Problem constants
#define BB 64
#define TT 1000
#define NN 512
#define G3 1536
#define SCAN_CTAS 128         // scan: 128 CTAs x 4 n-cols
#define WORK_CTAS 128         // xproj workers (co-resident, 2 CTAs/SM)
#define TOTAL_CTAS (SCAN_CTAS + WORK_CTAS)
#define YT 500                // xproj y-tiles (each covers 2 t-slices x 64 b)
#define XT 12                 // xproj x-tiles (1536/128)

typedef unsigned long long ull;

// ---------------------------------------------------------------------------
// f32x2 packed-FMA helpers (PTX-only; ptxas never auto-fuses)
// ---------------------------------------------------------------------------
__device__ __forceinline__ ull dup2(float x) {
    ull r; asm("mov.b64 %0, {%1, %1};" : "=l"(r) : "f"(x)); return r;
}
__device__ __forceinline__ void fma2(ull& d, ull a, ull b) {
    asm("fma.rn.f32x2 %0, %1, %2, %0;" : "+l"(d) : "l"(a), "l"(b));
}
__device__ __forceinline__ void add2(ull& d, ull a) {
    asm("add.rn.f32x2 %0, %0, %1;" : "+l"(d) : "l"(a));
}
__device__ __forceinline__ float2 unpack2(ull v) {
    float2 f; asm("mov.b64 {%0, %1}, %2;" : "=f"(f.x), "=f"(f.y) : "l"(v));
    return f;
}

// ---------------------------------------------------------------------------
// Scratch. Every sync word on its own 128B L2 line. Barrier = slot-store:
// each CTA release-stores its own line (parallel, no LTS atomic
// serialization); CTA 0 polls all slots and publishes g_gen.
// ---------------------------------------------------------------------------
struct __align__(128) Pad128 { unsigned v; unsigned pad[31]; };
__device__ Pad128   g_slot[SCAN_CTAS];              // per-CTA arrival slots
__device__ Pad128   g_gen;                          // generation (read-mostly)
__device__ Pad128   g_xdone[YT];                    // per-y-tile completion (==12)
__device__ float    g_xproj[(size_t)BB * TT * G3];  // TRANSPOSED: [t*64+b][3N]
__device__ float    g_ht[2][NN * BB];               // transposed hidden [k][b]

// SMEM pool offsets (bytes). Scan role sizes; worker uses first 16KB.
#define OFF_WSD 0                     // ull [3][2][512][2] = 49152
#define OFF_XS  49152                 // float [3][4][64]   = 3072
#define OFF_RED 52224                 // ull [8][3][4][32]  = 24576
#define OFF_HS  76800                 // float [4][64]      = 1024
#define SMEM_POOL 77824

// ---------------------------------------------------------------------------
// Init: reset all flags + zero h0 (must run every graph replay)
// ---------------------------------------------------------------------------
__global__ void init_kernel() {
    const int i = blockIdx.x * blockDim.x + threadIdx.x;
    if (i == 0) g_gen.v = 0u;
    if (i < SCAN_CTAS) g_slot[i].v = 0u;
    for (int j = i; j < YT; j += gridDim.x * blockDim.x) g_xdone[j].v = 0u;
    for (int j = i; j < NN * BB; j += gridDim.x * blockDim.x) g_ht[0][j] = 0.0f;
}

// ---------------------------------------------------------------------------
// Worker role (R14/R15-verified, unchanged): stream xproj tiles.
// ---------------------------------------------------------------------------
__device__ void xproj_worker(char* pool, int w,
                             const float* __restrict__ A,
                             const float* __restrict__ Wih,
                             const float* __restrict__ bih,
                             float* __restrict__ C) {
    float (*As)[128] = (float(*)[128])pool;            // [16][128] 8KB
    float (*Bs)[128] = (float(*)[128])(pool + 8192);   // [16][128] 8KB

    const int tid = threadIdx.x;
    const int tx = tid & 15;
    const int ty = tid >> 4;
    const int lr = tid >> 2;
    const int lk = (tid & 3) << 2;

    for (int idx = w; idx < YT * XT; idx += WORK_CTAS) {
        const int y = idx / XT;
        const int x = idx - y * XT;
        const int mBase = y * 128;
        const int nBase = x * 128;

        const int m0 = mBase + lr;
        const int b0 = m0 & 63;
        const int t0 = m0 >> 6;
        const float* Aptr = A + (size_t)(b0 * TT + t0) * NN + lk;
        const float* Bptr = Wih + (size_t)(nBase + lr) * NN + lk;

        ull acc2[8][4];
#pragma unroll
        for (int i = 0; i < 8; i++)
#pragma unroll
            for (int j = 0; j < 4; j++) acc2[i][j] = 0ull;

        for (int kt = 0; kt < NN; kt += 16) {
            const float4 a0 = *(const float4*)(Aptr + kt);
            const float4 a1 = *(const float4*)(Aptr + NN + kt);
            const float4 b0v = *(const float4*)(Bptr + kt);
            const float4 b1v = *(const float4*)(Bptr + 64 * NN + kt);
            __syncthreads();
            As[lk + 0][lr] = a0.x; As[lk + 1][lr] = a0.y; As[lk + 2][lr] = a0.z; As[lk + 3][lr] = a0.w;
            As[lk + 0][64 + lr] = a1.x; As[lk + 1][64 + lr] = a1.y; As[lk + 2][64 + lr] = a1.z; As[lk + 3][64 + lr] = a1.w;
            Bs[lk + 0][lr] = b0v.x; Bs[lk + 1][lr] = b0v.y; Bs[lk + 2][lr] = b0v.z; Bs[lk + 3][lr] = b0v.w;
            Bs[lk + 0][64 + lr] = b1v.x; Bs[lk + 1][64 + lr] = b1v.y; Bs[lk + 2][64 + lr] = b1v.z; Bs[lk + 3][64 + lr] = b1v.w;
            __syncthreads();
#pragma unroll
            for (int k = 0; k < 16; k++) {
                float af[8];
                *(float4*)&af[0] = *(const float4*)&As[k][ty * 4];
                *(float4*)&af[4] = *(const float4*)&As[k][64 + ty * 4];
                ull b2[4];
                *(uint4*)&b2[0] = *(const uint4*)&Bs[k][tx * 4];
                *(uint4*)&b2[2] = *(const uint4*)&Bs[k][64 + tx * 4];
#pragma unroll
                for (int i = 0; i < 8; i++) {
                    const ull ad = dup2(af[i]);
#pragma unroll
                    for (int j = 0; j < 4; j++) fma2(acc2[i][j], ad, b2[j]);
                }
            }
        }

        float bias[8];
#pragma unroll
        for (int j = 0; j < 8; j++) {
            int col = nBase + ((j < 4) ? (tx * 4 + j) : (64 + tx * 4 + (j - 4)));
            bias[j] = __ldg(&bih[col]);
        }
#pragma unroll
        for (int i = 0; i < 8; i++) {
            float a[8];
#pragma unroll
            for (int j = 0; j < 4; j++) {
                const float2 v = unpack2(acc2[i][j]);
                a[2 * j] = v.x; a[2 * j + 1] = v.y;
            }
            int row = mBase + ((i < 4) ? (ty * 4 + i) : (64 + ty * 4 + (i - 4)));
            float* cp = C + (size_t)row * G3 + nBase;
            *(float4*)(cp + tx * 4) =
                make_float4(a[0] + bias[0], a[1] + bias[1], a[2] + bias[2], a[3] + bias[3]);
            *(float4*)(cp + 64 + tx * 4) =
                make_float4(a[4] + bias[4], a[5] + bias[5], a[6] + bias[6], a[7] + bias[7]);
        }

        __threadfence();   // EACH thread: C stores -> gpu-scope visible
        __syncthreads();
        if (tid == 0) {
            unsigned dummy;
            asm volatile("atom.release.gpu.global.add.u32 %0, [%1], %2;"
                         : "=r"(dummy) : "l"(&g_xdone[y].v), "r"(1u) : "memory");
        }
    }
}

// ---------------------------------------------------------------------------
// Scan role: 128 CTAs x 256 threads, CTA owns 4 n-cols x 64 batches.
// RETILED: thread = (kq 0..7, nn2 0..1, b4 0..15): 64-k chunk, col pair
// (2*nn2, 2*nn2+1), 4 batches -> per k: 1 LDG.128 + 3 LDS.128 + 12 FFMA2.
// Each k-row read by exactly ONE warp (h wf halved); weights stored as
// adjacent dup'd col pairs (one LDS.128 = both cols for a gate).
// Barrier: per-CTA slot release-stores, CTA 0 polls + publishes.
// ---------------------------------------------------------------------------
__device__ void gru_scan(char* pool,
                         const float* __restrict__ Whh,
                         const float* __restrict__ bhh,
                         float* __restrict__ out) {
    ull   (*wsd)[2][512][2] = (ull(*)[2][512][2])(pool + OFF_WSD);  // [3][2][512][2]
    float (*xs)[4][64]      = (float(*)[4][64])(pool + OFF_XS);     // [3][4][64]
    ull   (*red)[3][4][32]  = (ull(*)[3][4][32])(pool + OFF_RED);   // [8][3][4][32]
    float (*hs)[64]         = (float(*)[64])(pool + OFF_HS);        // [4][64]

    const int tid = threadIdx.x;
    const int cid = blockIdx.x;
    const int n0  = cid * 4;
    const int kq  = tid >> 5;          // 0..7 (64-k chunk; == warp id)
    const int nn2 = (tid >> 4) & 1;    // col pair (2*nn2, 2*nn2+1)
    const int b4  = tid & 15;          // 4-batch group

    // Load + duplicate W_hh slice: [gate][nn2][k][colpair] (adjacent cols)
    for (int i = tid; i < 3 * 2 * 512; i += 256) {
        const int g  = i >> 10;            // gate 0..2
        const int n2 = (i >> 9) & 1;
        const int k  = i & 511;
        wsd[g][n2][k][0] = dup2(__ldg(&Whh[(size_t)(g * NN + n0 + 2 * n2) * NN + k]));
        wsd[g][n2][k][1] = dup2(__ldg(&Whh[(size_t)(g * NN + n0 + 2 * n2 + 1) * NN + k]));
    }

    // Epilogue biases (tid<128: en = tid>>5)
    float bhr = 0.f, bhz = 0.f, bhn = 0.f;
    if (tid < 128) {
        const int en = tid >> 5;
        bhr = __ldg(&bhh[n0 + en]);
        bhz = __ldg(&bhh[NN + n0 + en]);
        bhn = __ldg(&bhh[2 * NN + n0 + en]);
    }
    __syncthreads();

    for (int t = 0; t < TT; t++) {
        const float* __restrict__ hcur = g_ht[t & 1];
        float*       __restrict__ hnxt = g_ht[(t & 1) ^ 1];

        // Gate on xproj progress for this t-slice (usually already set)
        if (tid == 0) {
            const int y = t >> 1;
            unsigned d;
            while (true) {
                asm volatile("ld.acquire.gpu.global.u32 %0, [%1];"
                             : "=r"(d) : "l"(&g_xdone[y].v) : "memory");
                if (d >= (unsigned)XT) break;
                __nanosleep(64);
            }
        }
        __syncthreads();

        // Stage x_proj[t, :, slice] — PLAIN loads (concurrent peer writers)
        if (tid < 192) {
            const int gate = tid >> 6;
            const int b    = tid & 63;
            const float4 xv = *(const float4*)(
                g_xproj + (size_t)(t * BB + b) * G3 + gate * NN + n0);
            xs[gate][0][b] = xv.x; xs[gate][1][b] = xv.y;
            xs[gate][2][b] = xv.z; xs[gate][3][b] = xv.w;
        }

        // Mainloop: 64-k chunk, 2 cols, 4 batches -> 12 FFMA2/k
        ull a0r01 = 0, a0r23 = 0, a0z01 = 0, a0z23 = 0, a0n01 = 0, a0n23 = 0;
        ull a1r01 = 0, a1r23 = 0, a1z01 = 0, a1z23 = 0, a1n01 = 0, a1n23 = 0;
        const float* hk = hcur + kq * 64 * BB + b4 * 4;
        const ulonglong2* wrp = (const ulonglong2*)&wsd[0][nn2][kq * 64][0];
        const ulonglong2* wzp = (const ulonglong2*)&wsd[1][nn2][kq * 64][0];
        const ulonglong2* wnp = (const ulonglong2*)&wsd[2][nn2][kq * 64][0];
#pragma unroll 4
        for (int k = 0; k < 64; k++) {
            const ulonglong2 hv = *(const ulonglong2*)(hk + (size_t)k * BB);
            const ulonglong2 w0 = wrp[k];   // .x = col 2nn2, .y = col 2nn2+1
            const ulonglong2 w1 = wzp[k];
            const ulonglong2 w2 = wnp[k];
            fma2(a0r01, hv.x, w0.x); fma2(a0r23, hv.y, w0.x);
            fma2(a1r01, hv.x, w0.y); fma2(a1r23, hv.y, w0.y);
            fma2(a0z01, hv.x, w1.x); fma2(a0z23, hv.y, w1.x);
            fma2(a1z01, hv.x, w1.y); fma2(a1z23, hv.y, w1.y);
            fma2(a0n01, hv.x, w2.x); fma2(a0n23, hv.y, w2.x);
            fma2(a1n01, hv.x, w2.y); fma2(a1n23, hv.y, w2.y);
        }
        {
            const int c0 = 2 * nn2, c1 = 2 * nn2 + 1;
            *(ulonglong2*)&red[kq][0][c0][2 * b4] = make_ulonglong2(a0r01, a0r23);
            *(ulonglong2*)&red[kq][0][c1][2 * b4] = make_ulonglong2(a1r01, a1r23);
            *(ulonglong2*)&red[kq][1][c0][2 * b4] = make_ulonglong2(a0z01, a0z23);
            *(ulonglong2*)&red[kq][1][c1][2 * b4] = make_ulonglong2(a1z01, a1z23);
            *(ulonglong2*)&red[kq][2][c0][2 * b4] = make_ulonglong2(a0n01, a0n23);
            *(ulonglong2*)&red[kq][2][c1][2 * b4] = make_ulonglong2(a1n01, a1n23);
        }
        __syncthreads();

        // Epilogue: 128 threads, 2 batches each; sums 8 k-partials
        if (tid < 128) {
            const int en = tid >> 5;    // n-col 0..3
            const int eb = tid & 31;    // batch pair
            ull sr = red[0][0][en][eb];
            ull sz = red[0][1][en][eb];
            ull sq = red[0][2][en][eb];
#pragma unroll
            for (int q = 1; q < 8; q++) {
                add2(sr, red[q][0][en][eb]);
                add2(sz, red[q][1][en][eb]);
                add2(sq, red[q][2][en][eb]);
            }
            const float2 arf = unpack2(sr);
            const float2 azf = unpack2(sz);
            const float2 aqf = unpack2(sq);
            const float2 hp = *(const float2*)(hcur + (n0 + en) * BB + eb * 2);
            const float2 xr = *(const float2*)&xs[0][en][eb * 2];
            const float2 xz = *(const float2*)&xs[1][en][eb * 2];
            const float2 xn = *(const float2*)&xs[2][en][eb * 2];

            const float r0  = 1.0f / (1.0f + __expf(-(xr.x + arf.x + bhr)));
            const float z0  = 1.0f / (1.0f + __expf(-(xz.x + azf.x + bhz)));
            const float n0v = tanhf(xn.x + r0 * (aqf.x + bhn));
            const float h0  = (1.0f - z0) * n0v + z0 * hp.x;

            const float r1  = 1.0f / (1.0f + __expf(-(xr.y + arf.y + bhr)));
            const float z1  = 1.0f / (1.0f + __expf(-(xz.y + azf.y + bhz)));
            const float n1v = tanhf(xn.y + r1 * (aqf.y + bhn));
            const float h1  = (1.0f - z1) * n1v + z1 * hp.y;

            __stcg((float2*)(hnxt + (n0 + en) * BB + eb * 2), make_float2(h0, h1));
            hs[en][eb * 2 + 0] = h0;
            hs[en][eb * 2 + 1] = h1;
        }
        __syncthreads();   // hnxt + hs complete; safe to arrive

        // Out-writeback overlaps the barrier wait (out is never re-read).
        if (tid < 64) {
            const int b = tid;
            __stcg((float4*)(out + (size_t)(b * TT + t) * NN + n0),
                   make_float4(hs[0][b], hs[1][b], hs[2][b], hs[3][b]));
        }

        // Slot-store barrier: CTA release-stores its own line (parallel);
        // CTA 0's first 128 threads poll all slots (with backoff), bar,
        // publish g_gen.
        if (t < TT - 1) {
            const unsigned target = (unsigned)(t + 1);
            if (tid == 0) {
                asm volatile("st.release.gpu.global.u32 [%0], %1;"
                             :: "l"(&g_slot[cid].v), "r"(target) : "memory");
            }
            if (cid == 0) {
                if (tid < SCAN_CTAS) {
                    unsigned s;
                    while (true) {
                        asm volatile("ld.acquire.gpu.global.u32 %0, [%1];"
                                     : "=r"(s) : "l"(&g_slot[tid].v) : "memory");
                        if (s >= target) break;
                        __nanosleep(20);
                    }
                }
                __syncthreads();
                if (tid == 0) {
                    asm volatile("st.release.gpu.global.u32 [%0], %1;"
                                 :: "l"(&g_gen.v), "r"(target) : "memory");
                }
            } else {
                if (tid == 0) {
                    unsigned g;
                    while (true) {
                        asm volatile("ld.acquire.gpu.global.u32 %0, [%1];"
                                     : "=r"(g) : "l"(&g_gen.v) : "memory");
                        if (g >= target) break;
                        __nanosleep(32);
                    }
                }
                __syncthreads();
            }
            __threadfence();   // acquire: CCTL.IVALL so L1 h lines refresh
        }
    }
}

// ---------------------------------------------------------------------------
// Fused kernel, 2 CTAs/SM: CTAs 0..127 = scan, 128..255 = workers.
// All 256 CTAs co-resident in wave 1; workers terminate -> no deadlock.
// ---------------------------------------------------------------------------
__global__ void __launch_bounds__(256, 2) fused_kernel(
    const float* __restrict__ h_enc,
    const float* __restrict__ Wih,
    const float* __restrict__ Whh,
    const float* __restrict__ bih,
    const float* __restrict__ bhh,
    float* __restrict__ xproj,
    float* __restrict__ out) {
    extern __shared__ char pool[];
    if (blockIdx.x < SCAN_CTAS) {
        gru_scan(pool, Whh, bhh, out);
    } else {
        xproj_worker(pool, blockIdx.x - SCAN_CTAS, h_enc, Wih, bih, xproj);
    }
}

// ---------------------------------------------------------------------------
// Launch
// ---------------------------------------------------------------------------
extern "C" void kernel_launch(void* const* d_in, const int* in_sizes, int n_in,
                              void* d_out, int out_size) {
    const float* h_enc = (const float*)d_in[0];
    const float* W_ih  = (const float*)d_in[1];
    const float* W_hh  = (const float*)d_in[2];
    const float* b_ih  = (const float*)d_in[3];
    const float* b_hh  = (const float*)d_in[4];
    float* out = (float*)d_out;

    float* xproj_ptr = nullptr;
    cudaGetSymbolAddress((void**)&xproj_ptr, g_xproj);

    cudaFuncSetAttribute(fused_kernel,
                         cudaFuncAttributeMaxDynamicSharedMemorySize, SMEM_POOL);

    init_kernel<<<128, 256>>>();
    fused_kernel<<<TOTAL_CTAS, 256, SMEM_POOL>>>(
        h_enc, W_ih, W_hh, b_ih, b_hh, xproj_ptr, out);
}